// round 15
// baseline (speedup 1.0000x reference)
#include <cuda_runtime.h>
#include <math.h>

// Problem constants
#define B_    64
#define L_    512
#define C_    1024
#define NT    7
#define START_ 5
#define STOP_  6
#define NROWS (B_ * L_)   // 32768

// k1 tiling: 128 rows/block (4 warps x 32 rows), 32-col tiles,
// 4-deep PER-WARP cp.async ring (no block barriers in the mainloop).
#define RPB   128
#define TPB   128
#define KC    32
#define NTILE (C_ / KC)           // 32
#define NSTG  4
#define PADW  36                  // padded floats per smem row (conflict-free)
#define WSTG_BYTES (32 * PADW * 4)               // 4608 per warp-stage
#define SW_OFF     (4 * NSTG * WSTG_BYTES)       // 73728 (4 warps)
#define SW_BYTES   (NT * (C_ / 2) * 8)           // 28672
#define SB_OFF     (SW_OFF + SW_BYTES)
#define SMEM_BYTES (SB_OFF + 64)                 // ~102.5 KB -> 2 blocks/SM

// k2: 32 chunks x 16 steps, 256 threads
#define NCHK  32
#define CLEN  16
#define NFILL (L_ * NT / 256)     // 14 pred elements per thread

__device__ float g_nll[B_];
__device__ int   g_cnt;          // zero-init; self-resetting each run

// packed f32x2 FMA (Blackwell; PTX-only form -> single FFMA2)
__device__ __forceinline__ void ffma2(unsigned long long& d,
                                      unsigned long long a,
                                      unsigned long long b) {
    asm("fma.rn.f32x2 %0, %1, %2, %0;" : "+l"(d) : "l"(a), "l"(b));
}
__device__ __forceinline__ void lds_v2b64(unsigned smem_addr,
                                          unsigned long long& lo,
                                          unsigned long long& hi) {
    asm volatile("ld.shared.v2.b64 {%0, %1}, [%2];"
                 : "=l"(lo), "=l"(hi) : "r"(smem_addr));
}
__device__ __forceinline__ float unpack_sum(unsigned long long v) {
    union { unsigned long long u; float2 f; } cv; cv.u = v;
    return cv.f.x + cv.f.y;
}
__device__ __forceinline__ unsigned smem_u32(const void* p) {
    unsigned a;
    asm("{ .reg .u64 t; cvta.to.shared.u64 t, %1; cvt.u32.u64 %0, t; }"
        : "=r"(a) : "l"(p));
    return a;
}
// L1-ENABLED cp.async (.ca): goes through the L1 coalescer -> full-sector
// line wavefronts (the .cg bypass path issues sub-sector 16B requests).
__device__ __forceinline__ void cp_async16(unsigned dst, const void* src) {
    asm volatile("cp.async.ca.shared.global [%0], [%1], 16;"
                 :: "r"(dst), "l"(src));
}
__device__ __forceinline__ void cp_commit() {
    asm volatile("cp.async.commit_group;");
}
template <int N>
__device__ __forceinline__ void cp_wait() {
    asm volatile("cp.async.wait_group %0;" :: "n"(N));
}

// ---------------------------------------------------------------------------
// Kernel 1: pred = X @ W^T + b.  Thread-per-row; each WARP owns a private
// 4-deep cp.async pipeline over its 32 rows. W broadcast from shared as
// 16-byte vectors, f32x2 FMAs.
// ---------------------------------------------------------------------------
__global__ void __launch_bounds__(TPB) k1_gemm(
    const float* __restrict__ X, const int* __restrict__ labels,
    const float* __restrict__ W, const float* __restrict__ bias,
    float* __restrict__ out)
{
    extern __shared__ __align__(16) char dsm[];
    unsigned long long* sW2 = (unsigned long long*)(dsm + SW_OFF); // [NT][C_/2]
    float* sb = (float*)(dsm + SB_OFF);
    const unsigned sx_base = smem_u32(dsm);

    const int tid  = threadIdx.x;
    const int wid  = tid >> 5;
    const int lane = tid & 31;

    for (int i = tid; i < NT * (C_ / 2); i += TPB)
        sW2[i] = ((const unsigned long long*)W)[i];
    if (tid < NT) sb[tid] = bias[tid];
    __syncthreads();

    const int wrow0 = blockIdx.x * RPB + wid * 32;
    const float* xw = X + (size_t)wrow0 * C_;
    const unsigned wbase = sx_base + wid * (NSTG * WSTG_BYTES);

    #define LOAD_TILE(T, BUF) do {                                          \
        const float* sbse = xw + (T) * KC;                                  \
        unsigned dbse = wbase + (BUF) * WSTG_BYTES;                         \
        _Pragma("unroll")                                                   \
        for (int i_ = 0; i_ < 8; i_++) {                                    \
            int seg_ = i_ * 32 + lane;                                      \
            int r_ = seg_ >> 3, j_ = seg_ & 7;                              \
            cp_async16(dbse + r_ * (PADW * 4) + j_ * 16,                    \
                       sbse + (size_t)r_ * C_ + j_ * 4);                    \
        }                                                                   \
    } while (0)

    LOAD_TILE(0, 0); cp_commit();
    LOAD_TILE(1, 1); cp_commit();
    LOAD_TILE(2, 2); cp_commit();

    unsigned long long acc[NT];
    #pragma unroll
    for (int g = 0; g < NT; g++) acc[g] = 0ull;

    for (int t = 0; t < NTILE; t++) {
        if (t + 3 < NTILE) {
            LOAD_TILE(t + 3, (t + 3) & (NSTG - 1));
            cp_commit();
            cp_wait<3>();
        } else {
            cp_wait<0>();
        }
        __syncwarp();

        const unsigned rbase = wbase + (t & (NSTG - 1)) * WSTG_BYTES
                             + lane * (PADW * 4);
        const ulonglong2* wrow4 = (const ulonglong2*)(sW2 + t * (KC / 2));
        #pragma unroll
        for (int j = 0; j < 8; j++) {
            unsigned long long xlo, xhi;
            lds_v2b64(rbase + j * 16, xlo, xhi);
            #pragma unroll
            for (int g = 0; g < NT; g++) {
                const ulonglong2 wv = wrow4[g * (C_ / 4) + j];
                ffma2(acc[g], xlo, wv.x);
                ffma2(acc[g], xhi, wv.y);
            }
        }
        __syncwarp();
    }

    const int grow = wrow0 + lane;
    float* pred = out + 1 + NROWS;
    #pragma unroll
    for (int g = 0; g < NT; g++)
        pred[(size_t)grow * NT + g] = unpack_sum(acc[g]) + sb[g];
    out[1 + grow] = (float)labels[grow];
    #undef LOAD_TILE
}

// ---------------------------------------------------------------------------
// Kernel 2: CRF forward.  MLP-batched fill, labels staged in shared, then
// 32x16 chunked matrix products + binary-tree combine + gold + fused
// final reduction.
// ---------------------------------------------------------------------------
__global__ void __launch_bounds__(256) k2_crf(
    const float* __restrict__ trans,
    const int* __restrict__ labels,
    float* __restrict__ outbuf)
{
    __shared__ float sEE[L_ * 8];          // 16 KB exp-emissions
    __shared__ float sET[8][8];            // exp(transitions)
    __shared__ float sT[49];               // raw transitions
    __shared__ int   sLab[L_];             // labels for this batch (2 KB)
    __shared__ float sMa[NCHK][8][8];      // chunk matrices [c][col][row]
    __shared__ float sMb[NCHK / 2][8][8];  // tree ping-pong
    __shared__ float sS[NCHK];             // chunk log-scales
    __shared__ float sgred[8];
    __shared__ float svscale, sgold;
    __shared__ int   slast;

    const int b   = blockIdx.x;
    const int tid = threadIdx.x;
    const int base = b * L_;
    const float* pred = outbuf + 1 + NROWS;
    const float* pb = pred + (size_t)b * L_ * NT;

    // ---- Phase 0: batched independent loads (MLP = 16) ----
    float xv[NFILL];
    #pragma unroll
    for (int k = 0; k < NFILL; k++) xv[k] = pb[tid + k * 256];
    const int lv0 = labels[base + tid];
    const int lv1 = labels[base + tid + 256];

    #pragma unroll
    for (int k = 0; k < NFILL; k++) {
        const int i = tid + k * 256;
        sEE[(i / NT) * 8 + (i % NT)] = __expf(xv[k]);
    }
    #pragma unroll
    for (int k = 0; k < 2; k++)
        sEE[(tid + k * 256) * 8 + 7] = 0.f;
    sLab[tid] = lv0;
    sLab[tid + 256] = lv1;
    if (tid < 64) {
        int n = tid >> 3, p = tid & 7;
        sET[n][p] = (n < NT && p < NT) ? __expf(trans[n * NT + p]) : 0.f;
    }
    if (tid < 49) sT[tid] = trans[tid];
    __syncthreads();

    // ---- Stage A: per-chunk (16-step) matrix product, thread per column ----
    {
        const int chunk = tid >> 3;     // 0..31
        const int col   = tid & 7;      // 0..7 (7 = zero pad column)
        float ET[NT][NT];
        #pragma unroll
        for (int n = 0; n < NT; n++)
            #pragma unroll
            for (int p = 0; p < NT; p++) ET[n][p] = sET[n][p];

        const int t0 = chunk * CLEN;
        float u[NT];
        #pragma unroll
        for (int n = 0; n < NT; n++)
            u[n] = (col < NT) ? sET[n][col] * sEE[t0 * 8 + n] : 0.f;
        float s = 0.f;

        #pragma unroll 4
        for (int step = 1; step < CLEN; step++) {
            const float* ee = &sEE[(t0 + step) * 8];
            float v[NT];
            #pragma unroll
            for (int n = 0; n < NT; n++) {
                float a = ET[n][0] * u[0];
                #pragma unroll
                for (int p = 1; p < NT; p++) a = fmaf(ET[n][p], u[p], a);
                v[n] = a * ee[n];
            }
            #pragma unroll
            for (int n = 0; n < NT; n++) u[n] = v[n];

            if ((step & 7) == 7) {      // renorm at steps 7, 15
                float m = u[0];
                #pragma unroll
                for (int n = 1; n < NT; n++) m = fmaxf(m, u[n]);
                m = fmaxf(m, __shfl_xor_sync(0xffffffffu, m, 1));
                m = fmaxf(m, __shfl_xor_sync(0xffffffffu, m, 2));
                m = fmaxf(m, __shfl_xor_sync(0xffffffffu, m, 4));
                if (m > 0.f) {
                    float inv = __frcp_rn(m);
                    #pragma unroll
                    for (int n = 0; n < NT; n++) u[n] *= inv;
                    s += __logf(m);
                }
            }
        }
        #pragma unroll
        for (int n = 0; n < NT; n++) sMa[chunk][col][n] = u[n];
        sMa[chunk][col][7] = 0.f;
        if (col == 0) sS[chunk] = s;
    }

    // ---- Gold score (tags from shared; pred loads L1/L2-hot) ----
    {
        float acc = 0.f;
        #pragma unroll
        for (int k = 0; k < 2; k++) {
            const int t   = tid + k * 256;
            const int tag = sLab[t];
            const int pt  = (t == 0) ? START_ : sLab[t - 1];
            acc += pb[(size_t)t * NT + tag] + sT[tag * NT + pt];
        }
        #pragma unroll
        for (int o = 16; o > 0; o >>= 1)
            acc += __shfl_xor_sync(0xffffffffu, acc, o);
        if ((tid & 31) == 0) sgred[tid >> 5] = acc;
    }
    __syncthreads();

    if (tid == 0) {
        float g = 0.f;
        #pragma unroll
        for (int i = 0; i < 8; i++) g += sgred[i];
        sgold = g + sT[STOP_ * NT + sLab[L_ - 1]];
        float s = 0.f;
        #pragma unroll
        for (int i = 0; i < NCHK; i++) s += sS[i];
        svscale = s;
    }

    // ---- Tree combine: 5 levels of parallel 8x8 matrix products ----
    #define TREE_LEVEL(SRC, DST, NPAIR) do {                                \
        for (int idx = tid; idx < (NPAIR) * 64; idx += 256) {               \
            int k_ = idx >> 6, e_ = idx & 63;                               \
            int col_ = e_ >> 3, row_ = e_ & 7;                              \
            const float* A_ = &SRC[2 * k_][col_][0];                        \
            const float* Bv = &SRC[2 * k_ + 1][0][row_];                    \
            float a_ = Bv[0] * A_[0];                                       \
            _Pragma("unroll")                                               \
            for (int j_ = 1; j_ < 8; j_++)                                  \
                a_ = fmaf(Bv[j_ * 8], A_[j_], a_);                          \
            DST[k_][col_][row_] = a_;                                       \
        }                                                                   \
        __syncthreads();                                                    \
    } while (0)

    TREE_LEVEL(sMa, sMb, 16);
    TREE_LEVEL(sMb, sMa, 8);
    TREE_LEVEL(sMa, sMb, 4);
    TREE_LEVEL(sMb, sMa, 2);
    TREE_LEVEL(sMa, sMb, 1);
    #undef TREE_LEVEL

    if (tid == 0) {
        float sum = 0.f;
        #pragma unroll
        for (int n = 0; n < NT; n++)
            sum += sMb[0][START_][n] * sET[STOP_][n];
        g_nll[b] = __logf(sum) + svscale - sgold;
        __threadfence();
        slast = (atomicAdd(&g_cnt, 1) == B_ - 1);
    }
    __syncthreads();

    // Last block: deterministic sum of all 64 NLLs -> out[0]
    if (slast) {
        __shared__ float sred[64];
        __threadfence();
        if (tid < 64) sred[tid] = *((volatile float*)&g_nll[tid]);
        __syncthreads();
        if (tid < 32) sred[tid] += sred[tid + 32];
        __syncthreads();
        if (tid == 0) {
            float s = 0.f;
            #pragma unroll
            for (int i = 0; i < 32; i++) s += sred[i];
            outbuf[0] = s;
            g_cnt = 0;          // reset for next graph replay
        }
    }
}

extern "C" void kernel_launch(void* const* d_in, const int* in_sizes, int n_in,
                              void* d_out, int out_size)
{
    const float* X      = (const float*)d_in[0];
    const int*   labels = (const int*)  d_in[1];
    const float* W      = (const float*)d_in[2];
    const float* bias   = (const float*)d_in[3];
    const float* trans  = (const float*)d_in[4];
    float* out = (float*)d_out;

    static int smem_cfg = 0;
    if (!smem_cfg) {
        cudaFuncSetAttribute(k1_gemm,
                             cudaFuncAttributeMaxDynamicSharedMemorySize,
                             SMEM_BYTES);
        smem_cfg = 1;
    }

    k1_gemm<<<NROWS / RPB, TPB, SMEM_BYTES>>>(X, labels, W, bias, out);
    k2_crf<<<B_, 256>>>(trans, labels, out);
}

// round 17
// speedup vs baseline: 1.8369x; 1.8369x over previous
#include <cuda_runtime.h>
#include <math.h>

// Problem constants
#define B_    64
#define L_    512
#define C_    1024
#define NT    7
#define START_ 5
#define STOP_  6
#define NROWS (B_ * L_)   // 32768

// k1 tiling: 128 rows/block (4 warps x 32 rows), 32-col tiles,
// 4-deep PER-WARP cp.async ring (no block barriers in the mainloop).
#define RPB   128
#define TPB   128
#define KC    32
#define NTILE (C_ / KC)           // 32
#define NSTG  4
#define PADW  36                  // padded floats per smem row (conflict-free)
#define WSTG_BYTES (32 * PADW * 4)               // 4608 per warp-stage
#define SW_OFF     (4 * NSTG * WSTG_BYTES)       // 73728 (4 warps)
#define SW_BYTES   (NT * (C_ / 2) * 8)           // 28672
#define SB_OFF     (SW_OFF + SW_BYTES)
#define SMEM_BYTES (SB_OFF + 64)                 // ~102.5 KB -> 2 blocks/SM

// CRF chunking: 32 chunks x 16 steps per batch; 8 chunks per k1 block.
#define NCHK  32
#define CLEN  16

__device__ float g_chunkM[B_ * NCHK * 64];   // [b][chunk][col][row], 512 KB
__device__ float g_chunkS[B_ * NCHK];        // chunk log-scales
__device__ float g_gold[NROWS / RPB];        // per-k1-block gold partials
__device__ float g_nll[B_];
__device__ int   g_cnt;                      // zero-init; self-resetting

// packed f32x2 FMA (Blackwell; PTX-only form -> single FFMA2)
__device__ __forceinline__ void ffma2(unsigned long long& d,
                                      unsigned long long a,
                                      unsigned long long b) {
    asm("fma.rn.f32x2 %0, %1, %2, %0;" : "+l"(d) : "l"(a), "l"(b));
}
__device__ __forceinline__ void lds_v2b64(unsigned smem_addr,
                                          unsigned long long& lo,
                                          unsigned long long& hi) {
    asm volatile("ld.shared.v2.b64 {%0, %1}, [%2];"
                 : "=l"(lo), "=l"(hi) : "r"(smem_addr));
}
__device__ __forceinline__ float unpack_sum(unsigned long long v) {
    union { unsigned long long u; float2 f; } cv; cv.u = v;
    return cv.f.x + cv.f.y;
}
__device__ __forceinline__ unsigned smem_u32(const void* p) {
    unsigned a;
    asm("{ .reg .u64 t; cvta.to.shared.u64 t, %1; cvt.u32.u64 %0, t; }"
        : "=r"(a) : "l"(p));
    return a;
}
// L2-bypass-of-L1 path (.cg) — the right path for streaming (R15: .ca thrashes
// the tiny L1 under a 102KB smem carveout and halves throughput).
__device__ __forceinline__ void cp_async16(unsigned dst, const void* src) {
    asm volatile("cp.async.cg.shared.global [%0], [%1], 16;"
                 :: "r"(dst), "l"(src));
}
__device__ __forceinline__ void cp_commit() {
    asm volatile("cp.async.commit_group;");
}
template <int N>
__device__ __forceinline__ void cp_wait() {
    asm volatile("cp.async.wait_group %0;" :: "n"(N));
}

// ---------------------------------------------------------------------------
// Kernel 1: GEMM (pred = X @ W^T + b) + fused CRF Stage A + gold partials.
// Each block owns 128 rows = 8 CRF chunks of one batch-quarter; emissions are
// in registers at epilogue time, so Stage A costs no global re-read.
// ---------------------------------------------------------------------------
__global__ void __launch_bounds__(TPB) k1_gemm(
    const float* __restrict__ X, const int* __restrict__ labels,
    const float* __restrict__ W, const float* __restrict__ bias,
    const float* __restrict__ trans, float* __restrict__ out)
{
    extern __shared__ __align__(16) char dsm[];
    unsigned long long* sW2 = (unsigned long long*)(dsm + SW_OFF); // [NT][C_/2]
    float* sb = (float*)(dsm + SB_OFF);
    const unsigned sx_base = smem_u32(dsm);

    __shared__ float sET[8][8];     // exp(transitions)
    __shared__ float sT[49];        // raw transitions
    __shared__ float sgold2[2];

    const int tid  = threadIdx.x;
    const int wid  = tid >> 5;
    const int lane = tid & 31;

    for (int i = tid; i < NT * (C_ / 2); i += TPB)
        sW2[i] = ((const unsigned long long*)W)[i];
    if (tid < NT) sb[tid] = bias[tid];
    if (tid < 64) {
        int n = tid >> 3, p = tid & 7;
        sET[n][p] = (n < NT && p < NT) ? __expf(trans[n * NT + p]) : 0.f;
    }
    if (tid < 49) sT[tid] = trans[tid];
    __syncthreads();

    const int wrow0 = blockIdx.x * RPB + wid * 32;
    const float* xw = X + (size_t)wrow0 * C_;
    const unsigned wbase = sx_base + wid * (NSTG * WSTG_BYTES);

    #define LOAD_TILE(T, BUF) do {                                          \
        const float* sbse = xw + (T) * KC;                                  \
        unsigned dbse = wbase + (BUF) * WSTG_BYTES;                         \
        _Pragma("unroll")                                                   \
        for (int i_ = 0; i_ < 8; i_++) {                                    \
            int seg_ = i_ * 32 + lane;                                      \
            int r_ = seg_ >> 3, j_ = seg_ & 7;                              \
            cp_async16(dbse + r_ * (PADW * 4) + j_ * 16,                    \
                       sbse + (size_t)r_ * C_ + j_ * 4);                    \
        }                                                                   \
    } while (0)

    LOAD_TILE(0, 0); cp_commit();
    LOAD_TILE(1, 1); cp_commit();
    LOAD_TILE(2, 2); cp_commit();

    unsigned long long acc[NT];
    #pragma unroll
    for (int g = 0; g < NT; g++) acc[g] = 0ull;

    for (int t = 0; t < NTILE; t++) {
        if (t + 3 < NTILE) {
            LOAD_TILE(t + 3, (t + 3) & (NSTG - 1));
            cp_commit();
            cp_wait<3>();
        } else {
            cp_wait<0>();
        }
        __syncwarp();

        const unsigned rbase = wbase + (t & (NSTG - 1)) * WSTG_BYTES
                             + lane * (PADW * 4);
        const unsigned long long* wrow = sW2 + t * (KC / 2);
        #pragma unroll
        for (int j = 0; j < 8; j++) {
            unsigned long long xlo, xhi;
            lds_v2b64(rbase + j * 16, xlo, xhi);
            #pragma unroll
            for (int g = 0; g < NT; g++) {
                ffma2(acc[g], xlo, wrow[(size_t)g * (C_ / 2) + j * 2]);
                ffma2(acc[g], xhi, wrow[(size_t)g * (C_ / 2) + j * 2 + 1]);
            }
        }
        __syncwarp();
    }
    #undef LOAD_TILE

    // GEMM epilogue: results to global (pred + labels-as-float)
    const int grow = wrow0 + lane;
    const int myLab = labels[grow];
    float* pred = out + 1 + NROWS;
    float res[NT];
    #pragma unroll
    for (int g = 0; g < NT; g++) {
        res[g] = unpack_sum(acc[g]) + sb[g];
        pred[(size_t)grow * NT + g] = res[g];
    }
    out[1 + grow] = (float)myLab;

    // ---- All warps done with stage buffers -> overlay CRF scratch ----
    __syncthreads();
    float* sP = (float*)dsm;              // [128][8] raw emissions
    float* sE = (float*)(dsm + 4096);     // [128][8] exp(emissions)
    int*   sL = (int*)  (dsm + 8192);     // [128] labels
    {
        // local row == tid (grow = blockIdx*RPB + wid*32 + lane = base + tid)
        #pragma unroll
        for (int g = 0; g < NT; g++) {
            sP[tid * 8 + g] = res[g];
            sE[tid * 8 + g] = __expf(res[g]);
        }
        sE[tid * 8 + 7] = 0.f;
        sL[tid] = myLab;
    }
    __syncthreads();

    const int batch = blockIdx.x >> 2;
    const int q     = blockIdx.x & 3;

    if (tid < 64) {
        // ---- Stage A: 8 chunks x 8 columns (thread per column) ----
        const int lc  = tid >> 3;          // local chunk 0..7
        const int col = tid & 7;           // 0..7 (7 = zero pad column)
        const int gc  = q * 8 + lc;        // global chunk in batch
        const int t0  = lc * CLEN;         // local row offset
        float ET[NT][NT];
        #pragma unroll
        for (int n = 0; n < NT; n++)
            #pragma unroll
            for (int p = 0; p < NT; p++) ET[n][p] = sET[n][p];

        float u[NT];
        #pragma unroll
        for (int n = 0; n < NT; n++)
            u[n] = (col < NT) ? ET[n][col] * sE[t0 * 8 + n] : 0.f;
        float s = 0.f;

        #pragma unroll 4
        for (int step = 1; step < CLEN; step++) {
            const float* ee = &sE[(t0 + step) * 8];
            float v[NT];
            #pragma unroll
            for (int n = 0; n < NT; n++) {
                float a = ET[n][0] * u[0];
                #pragma unroll
                for (int p = 1; p < NT; p++) a = fmaf(ET[n][p], u[p], a);
                v[n] = a * ee[n];
            }
            #pragma unroll
            for (int n = 0; n < NT; n++) u[n] = v[n];

            if ((step & 7) == 7) {      // renorm at steps 7, 15
                float m = u[0];
                #pragma unroll
                for (int n = 1; n < NT; n++) m = fmaxf(m, u[n]);
                m = fmaxf(m, __shfl_xor_sync(0xffffffffu, m, 1));
                m = fmaxf(m, __shfl_xor_sync(0xffffffffu, m, 2));
                m = fmaxf(m, __shfl_xor_sync(0xffffffffu, m, 4));
                if (m > 0.f) {
                    float inv = __frcp_rn(m);
                    #pragma unroll
                    for (int n = 0; n < NT; n++) u[n] *= inv;
                    s += __logf(m);
                }
            }
        }
        float* dst = &g_chunkM[((size_t)(batch * NCHK + gc) * 8 + col) * 8];
        #pragma unroll
        for (int n = 0; n < NT; n++) dst[n] = u[n];
        dst[7] = 0.f;
        if (col == 0) g_chunkS[batch * NCHK + gc] = s;
    } else {
        // ---- Gold partial: threads 64..127, two consecutive tokens each ----
        const int i0 = (tid - 64) * 2;
        const int tag0 = sL[i0];
        const int tag1 = sL[i0 + 1];
        int prev0;
        if (i0 == 0)
            prev0 = (q == 0) ? START_ : labels[blockIdx.x * RPB - 1];
        else
            prev0 = sL[i0 - 1];
        float acc2 = sP[i0 * 8 + tag0]       + sT[tag0 * NT + prev0]
                   + sP[(i0 + 1) * 8 + tag1] + sT[tag1 * NT + tag0];
        #pragma unroll
        for (int o = 16; o > 0; o >>= 1)
            acc2 += __shfl_xor_sync(0xffffffffu, acc2, o);
        if (lane == 0) sgold2[wid - 2] = acc2;
    }
    __syncthreads();
    if (tid == 0) g_gold[blockIdx.x] = sgold2[0] + sgold2[1];
}

// ---------------------------------------------------------------------------
// Kernel 2: tiny combine — per batch: load 32 chunk matrices, 5-level tree,
// fixed-order scale/gold sums, final log; fused deterministic 64-way sum.
// ---------------------------------------------------------------------------
__global__ void __launch_bounds__(128) k2_combine(
    const float* __restrict__ trans,
    const int* __restrict__ labels,
    float* __restrict__ outbuf)
{
    __shared__ float sMa[NCHK][8][8];      // 8 KB
    __shared__ float sMb[NCHK / 2][8][8];  // 4 KB
    __shared__ float sETs[8];              // exp(trans[STOP][n])
    __shared__ int   slast;

    const int b   = blockIdx.x;
    const int tid = threadIdx.x;

    // Load 32 matrices (2048 floats) coalesced
    {
        const float4* src = (const float4*)&g_chunkM[(size_t)b * NCHK * 64];
        float4* dst = (float4*)sMa;
        #pragma unroll
        for (int k = 0; k < 4; k++) dst[tid + k * 128] = src[tid + k * 128];
    }
    if (tid < 8)
        sETs[tid] = (tid < NT) ? __expf(trans[STOP_ * NT + tid]) : 0.f;
    __syncthreads();

    // Tree combine: 5 levels of parallel 8x8 matrix products
    #define TREE_LEVEL(SRC, DST, NPAIR) do {                                \
        for (int idx = tid; idx < (NPAIR) * 64; idx += 128) {               \
            int k_ = idx >> 6, e_ = idx & 63;                               \
            int col_ = e_ >> 3, row_ = e_ & 7;                              \
            const float* A_ = &SRC[2 * k_][col_][0];                        \
            const float* Bv = &SRC[2 * k_ + 1][0][row_];                    \
            float a_ = Bv[0] * A_[0];                                       \
            _Pragma("unroll")                                               \
            for (int j_ = 1; j_ < 8; j_++)                                  \
                a_ = fmaf(Bv[j_ * 8], A_[j_], a_);                          \
            DST[k_][col_][row_] = a_;                                       \
        }                                                                   \
        __syncthreads();                                                    \
    } while (0)

    TREE_LEVEL(sMa, sMb, 16);
    TREE_LEVEL(sMb, sMa, 8);
    TREE_LEVEL(sMa, sMb, 4);
    TREE_LEVEL(sMb, sMa, 2);
    TREE_LEVEL(sMa, sMb, 1);
    #undef TREE_LEVEL

    if (tid == 0) {
        float scale = 0.f;
        #pragma unroll
        for (int i = 0; i < NCHK; i++) scale += g_chunkS[b * NCHK + i];
        float gold = g_gold[4 * b] + g_gold[4 * b + 1]
                   + g_gold[4 * b + 2] + g_gold[4 * b + 3]
                   + trans[STOP_ * NT + labels[b * L_ + L_ - 1]];
        float sum = 0.f;
        #pragma unroll
        for (int n = 0; n < NT; n++)
            sum += sMb[0][START_][n] * sETs[n];
        g_nll[b] = __logf(sum) + scale - gold;
        __threadfence();
        slast = (atomicAdd(&g_cnt, 1) == B_ - 1);
    }
    __syncthreads();

    // Last block: deterministic sum of all 64 NLLs -> out[0]
    if (slast) {
        __shared__ float sred[64];
        __threadfence();
        if (tid < 64) sred[tid] = *((volatile float*)&g_nll[tid]);
        __syncthreads();
        if (tid < 32) sred[tid] += sred[tid + 32];
        __syncthreads();
        if (tid == 0) {
            float s = 0.f;
            #pragma unroll
            for (int i = 0; i < 32; i++) s += sred[i];
            outbuf[0] = s;
            g_cnt = 0;          // reset for next graph replay
        }
    }
}

extern "C" void kernel_launch(void* const* d_in, const int* in_sizes, int n_in,
                              void* d_out, int out_size)
{
    const float* X      = (const float*)d_in[0];
    const int*   labels = (const int*)  d_in[1];
    const float* W      = (const float*)d_in[2];
    const float* bias   = (const float*)d_in[3];
    const float* trans  = (const float*)d_in[4];
    float* out = (float*)d_out;

    static int smem_cfg = 0;
    if (!smem_cfg) {
        cudaFuncSetAttribute(k1_gemm,
                             cudaFuncAttributeMaxDynamicSharedMemorySize,
                             SMEM_BYTES);
        smem_cfg = 1;
    }

    k1_gemm<<<NROWS / RPB, TPB, SMEM_BYTES>>>(X, labels, W, bias, trans, out);
    k2_combine<<<B_, 128>>>(trans, labels, out);
}